// round 8
// baseline (speedup 1.0000x reference)
#include <cuda_runtime.h>
#include <cuda_fp16.h>
#include <cstdint>

// ============================================================================
// NonLinODENet: dy/dt = tanh(y @ A^T + b), classical RK4, 40 steps.
// batch=524288, d=64.  GB300, but PTX target is baseline sm_103 (no 'a'),
// so NO tcgen05/TMEM — warp-level mma.sync.m16n8k16 (HMMA) instead.
//
//  - 1 CTA = 128 rows of y, resident in registers for all 160 f-evals.
//  - Per eval: Z[128,64] = Y[128,64] @ A^T[64,64] via mma.sync f16->f32.
//    A pre-split fp16 hi+lo (2 products: kills systematic A-quant drift).
//    Y single fp16 (error decorrelates per substep -> negligible).
//    Bias folded into the C operand of the first MMA of each n-tile.
//  - D-fragment layout == A-fragment layout for m16n8k16, so
//    tanh -> RK accumulate -> f16x2 repack is pure register work:
//    no shuffles, no SMEM staging, NO BARRIERS in the main loop.
//  - A^T fragments stored in SMEM in exact per-lane order -> LDS.64,
//    conflict-free, no ldmatrix.
// ============================================================================

#define RK_STEPS 40

__device__ __forceinline__ float tanh_fast(float x) {
    float r; asm("tanh.approx.f32 %0, %1;" : "=f"(r) : "f"(x)); return r;
}

// pack two f32 -> f16x2 {lo, hi}
__device__ __forceinline__ uint32_t pack_h2(float lo, float hi) {
    uint32_t d;
    asm("cvt.rn.f16x2.f32 %0, %1, %2;" : "=r"(d) : "f"(hi), "f"(lo));
    return d;
}

// robust scalar read: t_0/t_f may arrive as int32/int64 or float32
__device__ __forceinline__ float read_scalar(const void* p) {
    int iv = *(const int*)p;
    if (iv > -1000000 && iv < 1000000) return (float)iv;
    return *(const float*)p;
}

// D,C: 4 x f32.  A: 4 x .b32 (f16x2).  B: 2 x .b32 (f16x2).
#define MMA16816(d, a0_, a1_, a2_, a3_, b0_, b1_, c0_, c1_, c2_, c3_) \
    asm volatile("mma.sync.aligned.m16n8k16.row.col.f32.f16.f16.f32 " \
        "{%0,%1,%2,%3}, {%4,%5,%6,%7}, {%8,%9}, {%10,%11,%12,%13};" \
        : "=f"((d)[0]), "=f"((d)[1]), "=f"((d)[2]), "=f"((d)[3]) \
        : "r"(a0_), "r"(a1_), "r"(a2_), "r"(a3_), \
          "r"(b0_), "r"(b1_), \
          "f"(c0_), "f"(c1_), "f"(c2_), "f"(c3_))

// SMEM: B-operand fragments WB[hl][kt][nt][lane][reg], + bias
struct SmemT {
    uint32_t WB[2][4][8][32][2];  // 16 KB
    float bias[64];
};

__global__ __launch_bounds__(128, 2)
void NonLinODENet_kernel(const float* __restrict__ in,
                         const float* __restrict__ Amat,
                         const float* __restrict__ bvec,
                         const void* __restrict__ t0p,
                         const void* __restrict__ tfp,
                         float* __restrict__ out,
                         int nrows) {
    __shared__ SmemT sm;
    const int tid  = threadIdx.x;
    const int lane = tid & 31;
    const int w    = tid >> 5;
    const int g    = lane >> 2;   // groupID (fragment row within tile)
    const int t4   = lane & 3;    // thread-in-group (fragment col pair)

    // ---- prologue: W = A^T as B-operand fragments, fp16 hi + lo ----
    // B[k, n] = A[n, k]; per PTX m16n8k16 B layout:
    //   reg0 = {B[16kt+2t, 8nt+g], B[16kt+2t+1, ...]},  reg1 = +8 rows.
    for (int idx = tid; idx < 4096; idx += 128) {
        int r  = idx & 1;
        int ln = (idx >> 1) & 31;
        int nt = (idx >> 6) & 7;
        int kt = (idx >> 9) & 3;
        int hl = idx >> 11;
        int c  = ln >> 2, tt = ln & 3;
        int j  = 8 * nt + c;                 // output feature
        int k0 = 16 * kt + 8 * r + 2 * tt;   // input feature pair base
        float a0 = Amat[j * 64 + k0];
        float a1 = Amat[j * 64 + k0 + 1];
        float h0 = __half2float(__float2half_rn(a0));
        float h1 = __half2float(__float2half_rn(a1));
        float v0 = (hl == 0) ? a0 : (a0 - h0);
        float v1 = (hl == 0) ? a1 : (a1 - h1);
        sm.WB[hl][kt][nt][ln][r] = pack_h2(v0, v1);
    }
    if (tid < 64) sm.bias[tid] = bvec[tid];
    __syncthreads();

    // per-thread bias regs: columns j = 8nt + 2t + e
    float bj[8][2];
#pragma unroll
    for (int nt = 0; nt < 8; nt++) {
        bj[nt][0] = sm.bias[8 * nt + 2 * t4];
        bj[nt][1] = sm.bias[8 * nt + 2 * t4 + 1];
    }

    const float t0 = read_scalar(t0p);
    const float tf = read_scalar(tfp);
    const float dt  = (tf - t0) / (float)RK_STEPS;
    const float hdt = 0.5f * dt;
    const float dt6 = dt * (1.0f / 6.0f);

    // ---- y state in D/A-fragment layout ----
    // y[mt][nt][c]: c0,c1 -> row rowbase+16mt+g,   cols 8nt+2t+{0,1}
    //              c2,c3 -> row rowbase+16mt+g+8, same cols
    const int rowbase = blockIdx.x * 128 + w * 32;
    float y[2][8][4];
#pragma unroll
    for (int mt = 0; mt < 2; mt++) {
        int r0 = rowbase + 16 * mt + g;
        int r1 = r0 + 8;
#pragma unroll
        for (int nt = 0; nt < 8; nt++) {
            int col = 8 * nt + 2 * t4;
            if (r0 < nrows) {
                float2 v = *(const float2*)(in + (size_t)r0 * 64 + col);
                y[mt][nt][0] = v.x; y[mt][nt][1] = v.y;
            } else { y[mt][nt][0] = 0.f; y[mt][nt][1] = 0.f; }
            if (r1 < nrows) {
                float2 v = *(const float2*)(in + (size_t)r1 * 64 + col);
                y[mt][nt][2] = v.x; y[mt][nt][3] = v.y;
            } else { y[mt][nt][2] = 0.f; y[mt][nt][3] = 0.f; }
        }
    }

    // packed fp16 MMA input, in A-fragment-compatible order:
    // upk[mt][nt][0] = pack(c0,c1)  (row g),  [1] = pack(c2,c3) (row g+8)
    uint32_t upk[2][8][2];
#pragma unroll
    for (int mt = 0; mt < 2; mt++)
#pragma unroll
        for (int nt = 0; nt < 8; nt++) {
            upk[mt][nt][0] = pack_h2(y[mt][nt][0], y[mt][nt][1]);
            upk[mt][nt][1] = pack_h2(y[mt][nt][2], y[mt][nt][3]);
        }

    float acc[2][8][4];

    // ---- 160 f-evals, no barriers ----
#pragma unroll 1
    for (int ec = 0; ec < 4 * RK_STEPS; ++ec) {
        const int s = ec & 3;
        const float wgt  = (s == 1 || s == 2) ? 2.0f : 1.0f;
        const float cn   = (s == 2) ? dt : hdt;
        const bool first = (s == 0);
        const bool last  = (s == 3);

#pragma unroll
        for (int mt = 0; mt < 2; mt++) {
            float D[8][4];
#pragma unroll
            for (int nt = 0; nt < 8; nt++) {
                // kt=0, hi product, C = bias (fold bias into MMA)
                {
                    uint2 b = *(const uint2*)&sm.WB[0][0][nt][lane][0];
                    MMA16816(D[nt],
                             upk[mt][0][0], upk[mt][0][1],
                             upk[mt][1][0], upk[mt][1][1],
                             b.x, b.y,
                             bj[nt][0], bj[nt][1], bj[nt][0], bj[nt][1]);
                }
                // kt=0, lo product
                {
                    uint2 b = *(const uint2*)&sm.WB[1][0][nt][lane][0];
                    MMA16816(D[nt],
                             upk[mt][0][0], upk[mt][0][1],
                             upk[mt][1][0], upk[mt][1][1],
                             b.x, b.y,
                             D[nt][0], D[nt][1], D[nt][2], D[nt][3]);
                }
#pragma unroll
                for (int kt = 1; kt < 4; kt++) {
                    uint2 bh = *(const uint2*)&sm.WB[0][kt][nt][lane][0];
                    MMA16816(D[nt],
                             upk[mt][2 * kt][0], upk[mt][2 * kt][1],
                             upk[mt][2 * kt + 1][0], upk[mt][2 * kt + 1][1],
                             bh.x, bh.y,
                             D[nt][0], D[nt][1], D[nt][2], D[nt][3]);
                    uint2 bl = *(const uint2*)&sm.WB[1][kt][nt][lane][0];
                    MMA16816(D[nt],
                             upk[mt][2 * kt][0], upk[mt][2 * kt][1],
                             upk[mt][2 * kt + 1][0], upk[mt][2 * kt + 1][1],
                             bl.x, bl.y,
                             D[nt][0], D[nt][1], D[nt][2], D[nt][3]);
                }
            }

            // epilogue for this mt: tanh + RK update + repack (registers only)
#pragma unroll
            for (int nt = 0; nt < 8; nt++) {
                float u[4];
#pragma unroll
                for (int c = 0; c < 4; c++) {
                    float th = tanh_fast(D[nt][c]);   // bias already in D
                    float a  = first ? th : fmaf(wgt, th, acc[mt][nt][c]);
                    acc[mt][nt][c] = a;
                    float uu = fmaf(cn, th, y[mt][nt][c]);
                    if (last) {
                        float yn = fmaf(dt6, a, y[mt][nt][c]);
                        y[mt][nt][c] = yn;
                        uu = yn;
                    }
                    u[c] = uu;
                }
                upk[mt][nt][0] = pack_h2(u[0], u[1]);
                upk[mt][nt][1] = pack_h2(u[2], u[3]);
            }
        }
    }

    // ---- store final y ----
#pragma unroll
    for (int mt = 0; mt < 2; mt++) {
        int r0 = rowbase + 16 * mt + g;
        int r1 = r0 + 8;
#pragma unroll
        for (int nt = 0; nt < 8; nt++) {
            int col = 8 * nt + 2 * t4;
            if (r0 < nrows) {
                float2 v; v.x = y[mt][nt][0]; v.y = y[mt][nt][1];
                *(float2*)(out + (size_t)r0 * 64 + col) = v;
            }
            if (r1 < nrows) {
                float2 v; v.x = y[mt][nt][2]; v.y = y[mt][nt][3];
                *(float2*)(out + (size_t)r1 * 64 + col) = v;
            }
        }
    }
}

extern "C" void kernel_launch(void* const* d_in, const int* in_sizes, int n_in,
                              void* d_out, int out_size) {
    const float* in   = (const float*)d_in[0];
    const float* Amat = (const float*)d_in[1];
    const float* bvec = (const float*)d_in[2];
    const void*  t0p  = d_in[3];
    const void*  tfp  = d_in[4];
    float* out = (float*)d_out;

    int nrows = in_sizes[0] / 64;
    int grid = (nrows + 127) / 128;
    NonLinODENet_kernel<<<grid, 128>>>(in, Amat, bvec, t0p, tfp, out, nrows);
}

// round 15
// speedup vs baseline: 3.2157x; 3.2157x over previous
#include <cuda_runtime.h>
#include <cuda_fp16.h>
#include <cstdint>

// ============================================================================
// NonLinODENet: dy/dt = tanh(y @ A^T + b), classical RK4, 40 steps.
// batch=524288, d=64.  sm_103 baseline PTX -> mma.sync.m16n8k16 (HMMA).
//
// R8 measured: 5876us, rel_err 8.4e-6, L1=86% (bound: SMEM B reloads + 255-reg
// spills), tensor=40.5%, DRAM=0.6%.  This round:
//   - single fp16 A (drop hi/lo split): 2x less tensor work; rel_err budget
//     spent (est ~1e-4, gate is 1e-3; measured floor was 8.4e-6).
//   - B fragments entirely in REGISTERS (64 regs/thread): zero mainloop LDS.
//   - 256 thr/CTA, 16 rows/warp: per-thread state halved -> ~207 regs, no
//     spills (1 CTA x 256 thr x <=256 regs/SM).
//   - bias folded into C operand of first MMA; substeps compile-time unrolled;
//     no barriers/shuffles in mainloop.
// ============================================================================

#define RK_STEPS 40

__device__ __forceinline__ float tanh_fast(float x) {
    float r; asm("tanh.approx.f32 %0, %1;" : "=f"(r) : "f"(x)); return r;
}

// pack two f32 -> f16x2 {lo, hi}
__device__ __forceinline__ uint32_t pack_h2(float lo, float hi) {
    uint32_t d;
    asm("cvt.rn.f16x2.f32 %0, %1, %2;" : "=r"(d) : "f"(hi), "f"(lo));
    return d;
}

// robust scalar read: t_0/t_f may arrive as int32/int64 or float32
__device__ __forceinline__ float read_scalar(const void* p) {
    int iv = *(const int*)p;
    if (iv > -1000000 && iv < 1000000) return (float)iv;
    return *(const float*)p;
}

// D,C: 4 x f32.  A: 4 x .b32 (f16x2).  B: 2 x .b32 (f16x2).
#define MMA16816(d, a0_, a1_, a2_, a3_, b0_, b1_, c0_, c1_, c2_, c3_) \
    asm volatile("mma.sync.aligned.m16n8k16.row.col.f32.f16.f16.f32 " \
        "{%0,%1,%2,%3}, {%4,%5,%6,%7}, {%8,%9}, {%10,%11,%12,%13};" \
        : "=f"((d)[0]), "=f"((d)[1]), "=f"((d)[2]), "=f"((d)[3]) \
        : "r"(a0_), "r"(a1_), "r"(a2_), "r"(a3_), \
          "r"(b0_), "r"(b1_), \
          "f"(c0_), "f"(c1_), "f"(c2_), "f"(c3_))

__global__ __launch_bounds__(256, 1)
void NonLinODENet_kernel(const float* __restrict__ in,
                         const float* __restrict__ Amat,
                         const float* __restrict__ bvec,
                         const void* __restrict__ t0p,
                         const void* __restrict__ tfp,
                         float* __restrict__ out,
                         int nrows) {
    __shared__ float sA[64 * 64];
    __shared__ float sbias[64];

    const int tid  = threadIdx.x;
    const int lane = tid & 31;
    const int w    = tid >> 5;    // warp 0..7
    const int g    = lane >> 2;   // fragment row-in-tile / B col-in-tile
    const int t4   = lane & 3;    // fragment col pair

    // ---- stage A and bias ----
    for (int idx = tid; idx < 64 * 64; idx += 256) sA[idx] = Amat[idx];
    if (tid < 64) sbias[tid] = bvec[tid];
    __syncthreads();

    // ---- B fragments (A^T), fp16 rn, REGISTERS ----
    // B[k, n] = A[n, k].  m16n8k16 col-major B fragment:
    //   reg r: {B[16kt+8r+2t4, 8nt+g], B[16kt+8r+2t4+1, 8nt+g]}
    uint32_t wb[4][8][2];
#pragma unroll
    for (int kt = 0; kt < 4; kt++)
#pragma unroll
        for (int nt = 0; nt < 8; nt++)
#pragma unroll
            for (int r = 0; r < 2; r++) {
                int j  = 8 * nt + g;
                int k0 = 16 * kt + 8 * r + 2 * t4;
                wb[kt][nt][r] = pack_h2(sA[j * 64 + k0], sA[j * 64 + k0 + 1]);
            }

    // per-thread bias (C operand): cols j = 8nt + 2t4 + e
    float bj[8][2];
#pragma unroll
    for (int nt = 0; nt < 8; nt++) {
        bj[nt][0] = sbias[8 * nt + 2 * t4];
        bj[nt][1] = sbias[8 * nt + 2 * t4 + 1];
    }

    const float t0 = read_scalar(t0p);
    const float tf = read_scalar(tfp);
    const float dt  = (tf - t0) / (float)RK_STEPS;
    const float hdt = 0.5f * dt;
    const float dt6 = dt * (1.0f / 6.0f);

    // ---- y state, D/A-fragment layout: 16 rows per warp ----
    // y[nt][c]: c0,c1 -> row r0 = rowbase+g,  cols 8nt+2t4+{0,1}
    //           c2,c3 -> row r1 = r0+8,       same cols
    const int rowbase = blockIdx.x * 128 + w * 16;
    const int r0 = rowbase + g;
    const int r1 = r0 + 8;

    float y[8][4];
#pragma unroll
    for (int nt = 0; nt < 8; nt++) {
        int col = 8 * nt + 2 * t4;
        if (r0 < nrows) {
            float2 v = *(const float2*)(in + (size_t)r0 * 64 + col);
            y[nt][0] = v.x; y[nt][1] = v.y;
        } else { y[nt][0] = 0.f; y[nt][1] = 0.f; }
        if (r1 < nrows) {
            float2 v = *(const float2*)(in + (size_t)r1 * 64 + col);
            y[nt][2] = v.x; y[nt][3] = v.y;
        } else { y[nt][2] = 0.f; y[nt][3] = 0.f; }
    }

    // packed fp16 MMA input (A-fragment order): [0]=rows g, [1]=rows g+8
    uint32_t upk[8][2];
#pragma unroll
    for (int nt = 0; nt < 8; nt++) {
        upk[nt][0] = pack_h2(y[nt][0], y[nt][1]);
        upk[nt][1] = pack_h2(y[nt][2], y[nt][3]);
    }

    float acc[8][4];

    // ---- 40 steps x 4 substeps; zero SMEM traffic, zero barriers ----
#pragma unroll 1
    for (int step = 0; step < RK_STEPS; ++step) {
#pragma unroll
        for (int s = 0; s < 4; ++s) {
            const float wgt  = (s == 1 || s == 2) ? 2.0f : 1.0f;
            const float cn   = (s == 2) ? dt : hdt;
            const bool first = (s == 0);
            const bool last  = (s == 3);

            float D[8][4];
#pragma unroll
            for (int nt = 0; nt < 8; nt++) {
                // kt=0: C = bias (bias folded into the MMA)
                MMA16816(D[nt],
                         upk[0][0], upk[0][1], upk[1][0], upk[1][1],
                         wb[0][nt][0], wb[0][nt][1],
                         bj[nt][0], bj[nt][1], bj[nt][0], bj[nt][1]);
#pragma unroll
                for (int kt = 1; kt < 4; kt++)
                    MMA16816(D[nt],
                             upk[2 * kt][0], upk[2 * kt][1],
                             upk[2 * kt + 1][0], upk[2 * kt + 1][1],
                             wb[kt][nt][0], wb[kt][nt][1],
                             D[nt][0], D[nt][1], D[nt][2], D[nt][3]);
            }

            // epilogue: tanh + RK update + repack (registers only)
#pragma unroll
            for (int nt = 0; nt < 8; nt++) {
                float u[4];
#pragma unroll
                for (int c = 0; c < 4; c++) {
                    float th = tanh_fast(D[nt][c]);
                    float a  = first ? th : fmaf(wgt, th, acc[nt][c]);
                    acc[nt][c] = a;
                    float uu = fmaf(cn, th, y[nt][c]);
                    if (last) {
                        float yn = fmaf(dt6, a, y[nt][c]);
                        y[nt][c] = yn;
                        uu = yn;
                    }
                    u[c] = uu;
                }
                upk[nt][0] = pack_h2(u[0], u[1]);
                upk[nt][1] = pack_h2(u[2], u[3]);
            }
        }
    }

    // ---- store final y ----
#pragma unroll
    for (int nt = 0; nt < 8; nt++) {
        int col = 8 * nt + 2 * t4;
        if (r0 < nrows) {
            float2 v; v.x = y[nt][0]; v.y = y[nt][1];
            *(float2*)(out + (size_t)r0 * 64 + col) = v;
        }
        if (r1 < nrows) {
            float2 v; v.x = y[nt][2]; v.y = y[nt][3];
            *(float2*)(out + (size_t)r1 * 64 + col) = v;
        }
    }
}

extern "C" void kernel_launch(void* const* d_in, const int* in_sizes, int n_in,
                              void* d_out, int out_size) {
    const float* in   = (const float*)d_in[0];
    const float* Amat = (const float*)d_in[1];
    const float* bvec = (const float*)d_in[2];
    const void*  t0p  = d_in[3];
    const void*  tfp  = d_in[4];
    float* out = (float*)d_out;

    int nrows = in_sizes[0] / 64;
    int grid = (nrows + 127) / 128;
    NonLinODENet_kernel<<<grid, 256>>>(in, Amat, bvec, t0p, tfp, out, nrows);
}